// round 6
// baseline (speedup 1.0000x reference)
#include <cuda_runtime.h>
#include <math_constants.h>

#define N 384
#define D 128
#define HD 64                 // half row
#define MARGIN 0.2f
#define RHO 10.0f
#define GA 3                  // anchors per block
#define NBLK (N / GA)         // 128 blocks = one wave
#define NT 768                // 2 halves x 384 rows
#define NWARP (NT / 32)       // 24

__device__ double g_num;
__device__ int    g_den;
__device__ int    g_count;    // zero-init; last block resets each replay

__global__ void __launch_bounds__(NT, 1)
facenet_kernel(const int* __restrict__ classes,
               const float* __restrict__ emb,
               float* __restrict__ out) {
    __shared__ __align__(16) float anc[GA][D];
    __shared__ float  pd[2][GA][N];   // partial dots per half
    __shared__ float  psq[2][N];      // partial squared norms
    __shared__ float  drow[GA][N];    // distances
    __shared__ float  dval[GA][N];    // valid-negative distances (else +INF)
    __shared__ float  sqv[N];
    __shared__ int    cls[N];
    __shared__ short  poslist[GA][N];
    __shared__ int    npos[GA];
    __shared__ double warpsum[NWARP];
    __shared__ bool   islast;

    const int tid  = threadIdx.x;
    const int h    = (tid >= N) ? 1 : 0;   // which half of the row
    const int k    = tid - h * N;          // row index 0..383
    const int base = blockIdx.x * GA;

    // ---- issue all cold loads up front (classes, anchors, own row half) ----
    if (tid < N) cls[tid] = classes[tid];
    if (tid < GA) npos[tid] = 0;
    if (tid < GA * D)                       // 384 anchor floats
        anc[tid / D][tid % D] = emb[base * D + tid];

    const float4* rowk = reinterpret_cast<const float4*>(emb + k * D + h * HD); // 16 chunks
    float4 buf[4];
#pragma unroll
    for (int q = 0; q < 4; q++) buf[q] = rowk[q];

    __syncthreads();

    // ---- half-row dots with 3 anchors + half squared norm ----
    {
        const float4* A0 = reinterpret_cast<const float4*>(anc[0] + h * HD);
        const float4* A1 = reinterpret_cast<const float4*>(anc[1] + h * HD);
        const float4* A2 = reinterpret_cast<const float4*>(anc[2] + h * HD);
        float d0 = 0.f, d1 = 0.f, d2 = 0.f, sq = 0.f;
#pragma unroll
        for (int qq = 0; qq < 16; qq += 4) {
            float4 cur[4];
#pragma unroll
            for (int q = 0; q < 4; q++) cur[q] = buf[q];
            if (qq + 4 < 16) {
#pragma unroll
                for (int q = 0; q < 4; q++) buf[q] = rowk[qq + 4 + q];
            }
#pragma unroll
            for (int q = 0; q < 4; q++) {
                const float4 v  = cur[q];
                const float4 w0 = A0[qq + q];
                const float4 w1 = A1[qq + q];
                const float4 w2 = A2[qq + q];
                sq = fmaf(v.x, v.x, fmaf(v.y, v.y, fmaf(v.z, v.z, fmaf(v.w, v.w, sq))));
                d0 = fmaf(v.x, w0.x, fmaf(v.y, w0.y, fmaf(v.z, w0.z, fmaf(v.w, w0.w, d0))));
                d1 = fmaf(v.x, w1.x, fmaf(v.y, w1.y, fmaf(v.z, w1.z, fmaf(v.w, w1.w, d1))));
                d2 = fmaf(v.x, w2.x, fmaf(v.y, w2.y, fmaf(v.z, w2.z, fmaf(v.w, w2.w, d2))));
            }
        }
        pd[h][0][k] = d0;
        pd[h][1][k] = d1;
        pd[h][2][k] = d2;
        psq[h][k]   = sq;
    }
    __syncthreads();

    // ---- combine halves (threads 0..383), publish sqv + dots ----
    if (tid < N) {
        sqv[k]     = psq[0][k] + psq[1][k];
        drow[0][k] = pd[0][0][k] + pd[1][0][k];
        drow[1][k] = pd[0][1][k] + pd[1][1][k];
        drow[2][k] = pd[0][2][k] + pd[1][2][k];
    }
    __syncthreads();

    // ---- distances, masked arrays, positive-pair lists ----
    if (tid < N) {
        const float sqk = sqv[k];
        const int   ck  = cls[k];
#pragma unroll
        for (int g = 0; g < GA; g++) {
            const int a = base + g;
            float dist = fmaxf(sqv[a] + sqk - 2.0f * drow[g][k], 0.0f);
            drow[g][k] = dist;
            bool same = (ck == cls[a]);
            dval[g][k] = same ? CUDART_INF_F : dist;   // valid negatives only
            if (same && k != a) {
                int p = atomicAdd(&npos[g], 1);
                poslist[g][p] = (short)k;
            }
        }
    }
    __syncthreads();

    const int np0 = npos[0], np1 = npos[1], np2 = npos[2];
    const int ntot = np0 + np1 + np2;
    if (tid == 0 && ntot > 0) atomicAdd(&g_den, ntot);

    // ---- per-pair scans: warp per pair (24 warps, ~21 pairs) ----
    const int warp = tid >> 5;
    const int lane = tid & 31;
    double wsum = 0.0;

    for (int p = warp; p < ntot; p += NWARP) {
        int g, l;
        if (p < np0)            { g = 0; l = p; }
        else if (p < np0 + np1) { g = 1; l = p - np0; }
        else                    { g = 2; l = p - np0 - np1; }

        const float t = drow[g][poslist[g][l]];   // d(i, j)
        const float* dv = dval[g];

        float minw = CUDART_INF_F;    // min x in [0, MARGIN)
        float maxn = -CUDART_INF_F;   // max x < 0
#pragma unroll
        for (int kk = 0; kk < N / 32; kk++) {
            float x = dv[kk * 32 + lane] - t;     // d(i,k) - d(i,j)
            minw = fminf(minw, (x >= 0.0f && x < MARGIN) ? x : CUDART_INF_F);
            maxn = fmaxf(maxn, (x < 0.0f) ? x : -CUDART_INF_F);
        }
#pragma unroll
        for (int off = 16; off; off >>= 1) {
            minw = fminf(minw, __shfl_xor_sync(0xffffffffu, minw, off));
            maxn = fmaxf(maxn, __shfl_xor_sync(0xffffffffu, maxn, off));
        }
        // semihard: max loss = MARGIN - minw; hard: min loss = MARGIN - maxn
        float semimax = (minw < CUDART_INF_F) ? (MARGIN - minw) : 0.0f;
        float minhard = MARGIN - maxn;            // +INF if no hard k
        float pph = (minhard < RHO) ? minhard : 0.0f;
        wsum += (double)((semimax > 0.0f) ? semimax : pph);
    }

    if (lane == 0) warpsum[warp] = wsum;
    __syncthreads();

    if (tid == 0) {
        double s = 0.0;
#pragma unroll
        for (int w = 0; w < NWARP; w++) s += warpsum[w];
        if (s != 0.0) atomicAdd(&g_num, s);
        __threadfence();
        int c = atomicAdd(&g_count, 1);
        islast = (c == NBLK - 1);
    }
    __syncthreads();

    // ---- last block finalizes + resets for the next graph replay ----
    if (islast && tid == 0) {
        double num = *(volatile double*)&g_num;   // ordered by fence+counter
        int    den = *(volatile int*)&g_den;
        double r = (den > 0) ? (num / fmax((double)den, 1.0)) : 0.0;
        out[0] = (float)r;
        g_num = 0.0;
        g_den = 0;
        __threadfence();
        g_count = 0;
    }
}

extern "C" void kernel_launch(void* const* d_in, const int* in_sizes, int n_in,
                              void* d_out, int out_size) {
    const int*   classes = (const int*)d_in[0];
    const float* emb     = (const float*)d_in[1];
    facenet_kernel<<<NBLK, NT>>>(classes, emb, (float*)d_out);
}

// round 7
// speedup vs baseline: 1.0152x; 1.0152x over previous
#include <cuda_runtime.h>
#include <math_constants.h>

#define N 384
#define D 128
#define HD 64                 // half row
#define MARGIN 0.2f
#define RHO 10.0f
#define GA 3                  // anchors per block
#define NBLK (N / GA)         // 128 blocks = one wave
#define NT 768                // 2 halves x 384 rows
#define NWARP (NT / 32)       // 24

typedef unsigned long long u64;

__device__ __forceinline__ u64 ffma2(u64 a, u64 b, u64 c) {
    u64 d;
    asm("fma.rn.f32x2 %0, %1, %2, %3;" : "=l"(d) : "l"(a), "l"(b), "l"(c));
    return d;
}
__device__ __forceinline__ float f2sum(u64 v) {
    float lo, hi;
    asm("mov.b64 {%0, %1}, %2;" : "=f"(lo), "=f"(hi) : "l"(v));
    return lo + hi;
}

__device__ double g_num;
__device__ int    g_den;
__device__ int    g_count;    // zero-init; last block resets each replay

__global__ void __launch_bounds__(NT, 1)
facenet_kernel(const int* __restrict__ classes,
               const float* __restrict__ emb,
               float* __restrict__ out) {
    __shared__ __align__(16) float anc[GA][D];
    __shared__ float  pd[2][GA][N];   // partial dots per half
    __shared__ float  psq[2][N];      // partial squared norms
    __shared__ float  drow[GA][N];    // distances
    __shared__ float  dval[GA][N];    // valid-negative distances (else +INF)
    __shared__ float  sqv[N];
    __shared__ int    cls[N];
    __shared__ short  poslist[GA][N];
    __shared__ int    npos[GA];
    __shared__ double warpsum[NWARP];
    __shared__ bool   islast;

    const int tid  = threadIdx.x;
    const int h    = (tid >= N) ? 1 : 0;   // which half of the row
    const int k    = tid - h * N;          // row index 0..383
    const int base = blockIdx.x * GA;

    // ---- issue all cold loads up front (classes, anchors, own row half) ----
    if (tid < N) cls[tid] = classes[tid];
    if (tid < GA) npos[tid] = 0;
    if (tid < GA * D)                       // 384 anchor floats
        anc[tid / D][tid % D] = emb[base * D + tid];

    // own half-row: 64 floats = 16 x 16B chunks
    const ulonglong2* rowk = reinterpret_cast<const ulonglong2*>(emb + k * D + h * HD);
    ulonglong2 buf[4];
#pragma unroll
    for (int q = 0; q < 4; q++) buf[q] = rowk[q];   // overlap with barrier

    __syncthreads();

    // ---- packed-f32x2 half-row dots with 3 anchors + half squared norm ----
    {
        const ulonglong2* A0 = reinterpret_cast<const ulonglong2*>(anc[0] + h * HD);
        const ulonglong2* A1 = reinterpret_cast<const ulonglong2*>(anc[1] + h * HD);
        const ulonglong2* A2 = reinterpret_cast<const ulonglong2*>(anc[2] + h * HD);
        u64 d0x = 0, d0y = 0, d1x = 0, d1y = 0, d2x = 0, d2y = 0, sqx = 0, sqy = 0;

#pragma unroll
        for (int qq = 0; qq < 16; qq += 4) {
            ulonglong2 cur[4];
#pragma unroll
            for (int q = 0; q < 4; q++) cur[q] = buf[q];
            if (qq + 4 < 16) {
#pragma unroll
                for (int q = 0; q < 4; q++) buf[q] = rowk[qq + 4 + q];
            }
#pragma unroll
            for (int q = 0; q < 4; q++) {
                const ulonglong2 v  = cur[q];
                const ulonglong2 w0 = A0[qq + q];
                const ulonglong2 w1 = A1[qq + q];
                const ulonglong2 w2 = A2[qq + q];
                sqx = ffma2(v.x, v.x, sqx);  sqy = ffma2(v.y, v.y, sqy);
                d0x = ffma2(v.x, w0.x, d0x); d0y = ffma2(v.y, w0.y, d0y);
                d1x = ffma2(v.x, w1.x, d1x); d1y = ffma2(v.y, w1.y, d1y);
                d2x = ffma2(v.x, w2.x, d2x); d2y = ffma2(v.y, w2.y, d2y);
            }
        }
        pd[h][0][k] = f2sum(d0x) + f2sum(d0y);
        pd[h][1][k] = f2sum(d1x) + f2sum(d1y);
        pd[h][2][k] = f2sum(d2x) + f2sum(d2y);
        psq[h][k]   = f2sum(sqx) + f2sum(sqy);
    }
    __syncthreads();

    // ---- combine halves (threads 0..383) ----
    if (tid < N) {
        sqv[k]     = psq[0][k] + psq[1][k];
        drow[0][k] = pd[0][0][k] + pd[1][0][k];
        drow[1][k] = pd[0][1][k] + pd[1][1][k];
        drow[2][k] = pd[0][2][k] + pd[1][2][k];
    }
    __syncthreads();

    // ---- distances, masked arrays, positive-pair lists ----
    if (tid < N) {
        const float sqk = sqv[k];
        const int   ck  = cls[k];
#pragma unroll
        for (int g = 0; g < GA; g++) {
            const int a = base + g;
            float dist = fmaxf(sqv[a] + sqk - 2.0f * drow[g][k], 0.0f);
            drow[g][k] = dist;
            bool same = (ck == cls[a]);
            dval[g][k] = same ? CUDART_INF_F : dist;   // valid negatives only
            if (same && k != a) {
                int p = atomicAdd(&npos[g], 1);
                poslist[g][p] = (short)k;
            }
        }
    }
    __syncthreads();

    const int np0 = npos[0], np1 = npos[1], np2 = npos[2];
    const int ntot = np0 + np1 + np2;
    if (tid == 0 && ntot > 0) atomicAdd(&g_den, ntot);

    // ---- per-pair scans: warp per pair (24 warps, ~21 pairs) ----
    const int warp = tid >> 5;
    const int lane = tid & 31;
    double wsum = 0.0;

    for (int p = warp; p < ntot; p += NWARP) {
        int g, l;
        if (p < np0)            { g = 0; l = p; }
        else if (p < np0 + np1) { g = 1; l = p - np0; }
        else                    { g = 2; l = p - np0 - np1; }

        const float t = drow[g][poslist[g][l]];   // d(i, j)
        const float* dv = dval[g];

        float minw = CUDART_INF_F;    // min x in [0, MARGIN)
        float maxn = -CUDART_INF_F;   // max x < 0
#pragma unroll
        for (int kk = 0; kk < N / 32; kk++) {
            float x = dv[kk * 32 + lane] - t;     // d(i,k) - d(i,j)
            minw = fminf(minw, (x >= 0.0f && x < MARGIN) ? x : CUDART_INF_F);
            maxn = fmaxf(maxn, (x < 0.0f) ? x : -CUDART_INF_F);
        }
#pragma unroll
        for (int off = 16; off; off >>= 1) {
            minw = fminf(minw, __shfl_xor_sync(0xffffffffu, minw, off));
            maxn = fmaxf(maxn, __shfl_xor_sync(0xffffffffu, maxn, off));
        }
        float semimax = (minw < CUDART_INF_F) ? (MARGIN - minw) : 0.0f;
        float minhard = MARGIN - maxn;            // +INF if no hard k
        float pph = (minhard < RHO) ? minhard : 0.0f;
        wsum += (double)((semimax > 0.0f) ? semimax : pph);
    }

    if (lane == 0) warpsum[warp] = wsum;
    __syncthreads();

    if (tid == 0) {
        double s = 0.0;
#pragma unroll
        for (int w = 0; w < NWARP; w++) s += warpsum[w];
        if (s != 0.0) atomicAdd(&g_num, s);
        __threadfence();
        int c = atomicAdd(&g_count, 1);
        islast = (c == NBLK - 1);
    }
    __syncthreads();

    // ---- last block finalizes + resets for the next graph replay ----
    if (islast && tid == 0) {
        double num = *(volatile double*)&g_num;   // ordered by fence+counter
        int    den = *(volatile int*)&g_den;
        double r = (den > 0) ? (num / fmax((double)den, 1.0)) : 0.0;
        out[0] = (float)r;
        g_num = 0.0;
        g_den = 0;
        __threadfence();
        g_count = 0;
    }
}

extern "C" void kernel_launch(void* const* d_in, const int* in_sizes, int n_in,
                              void* d_out, int out_size) {
    const int*   classes = (const int*)d_in[0];
    const float* emb     = (const float*)d_in[1];
    facenet_kernel<<<NBLK, NT>>>(classes, emb, (float*)d_out);
}